// round 10
// baseline (speedup 1.0000x reference)
#include <cuda_runtime.h>
#include <cuda_bf16.h>
#include <cstddef>
#include <cstdint>

#define NMAX 50000
#define EMAX 600000
#define CCH 128
#define SLOTS 64

// ---------------- scratch (static device globals; no allocation) -------------
__device__ float g_y[(size_t)NMAX * CCH];
__device__ float g_h[(size_t)NMAX * CCH];
__device__ int   g_cnt[NMAX];
__device__ int   g_slot[(size_t)NMAX * SLOTS];
__device__ int   g_src[(size_t)NMAX * SLOTS];
__device__ float g_sum[CCH];
__device__ float g_sumsq[CCH];
__device__ __nv_bfloat16 g_xh[(size_t)NMAX * CCH];
__device__ __nv_bfloat16 g_xl[(size_t)NMAX * CCH];
__device__ __nv_bfloat16 g_wh[2 * CCH * CCH];
__device__ __nv_bfloat16 g_wl[2 * CCH * CCH];

// ---------------- zero per-launch state ----------------
__global__ void k_zero(int n) {
    int i = blockIdx.x * blockDim.x + threadIdx.x;
    if (i < n) g_cnt[i] = 0;
    if (i < CCH) { g_sum[i] = 0.f; g_sumsq[i] = 0.f; }
}

// ---------------- bucket fill (slot = edge id, src prevalidated) -------------
__global__ void k_bucket(const int* __restrict__ ei, int nE, int n) {
    int e = blockIdx.x * blockDim.x + threadIdx.x;
    if (e < nE) {
        int t = ei[nE + e];                       // row 1 = target
        if ((unsigned)t < (unsigned)n) {
            int p = atomicAdd(&g_cnt[t], 1);
            if (p < SLOTS) {
                int s = ei[e];                    // row 0 = source
                if ((unsigned)s >= (unsigned)n) s = 0;
                g_slot[(size_t)t * SLOTS + p] = e;
                g_src [(size_t)t * SLOTS + p] = s;
            }
        }
    }
}

// ---------------- bf16 hi/lo split conversion of x, Wg, Wl ------------------
__device__ __forceinline__ void split4(float4 v, uint2& h, uint2& l) {
    __nv_bfloat16 hx = __float2bfloat16(v.x);
    __nv_bfloat16 hy = __float2bfloat16(v.y);
    __nv_bfloat16 hz = __float2bfloat16(v.z);
    __nv_bfloat16 hw = __float2bfloat16(v.w);
    __nv_bfloat16 lx = __float2bfloat16(v.x - __bfloat162float(hx));
    __nv_bfloat16 ly = __float2bfloat16(v.y - __bfloat162float(hy));
    __nv_bfloat16 lz = __float2bfloat16(v.z - __bfloat162float(hz));
    __nv_bfloat16 lw = __float2bfloat16(v.w - __bfloat162float(hw));
    h.x = ((unsigned)__bfloat16_as_ushort(hy) << 16) | __bfloat16_as_ushort(hx);
    h.y = ((unsigned)__bfloat16_as_ushort(hw) << 16) | __bfloat16_as_ushort(hz);
    l.x = ((unsigned)__bfloat16_as_ushort(ly) << 16) | __bfloat16_as_ushort(lx);
    l.y = ((unsigned)__bfloat16_as_ushort(lw) << 16) | __bfloat16_as_ushort(lz);
}

__global__ void k_cvt(const float* __restrict__ x,
                      const float* __restrict__ Wg,
                      const float* __restrict__ Wl, int n) {
    int idx = blockIdx.x * blockDim.x + threadIdx.x;
    int tx4 = n * (CCH / 4);
    if (idx < tx4) {
        float4 v = ((const float4*)x)[idx];
        uint2 h, l;
        split4(v, h, l);
        ((uint2*)g_xh)[idx] = h;
        ((uint2*)g_xl)[idx] = l;
    } else if (idx < tx4 + 2 * CCH * CCH / 4) {
        int j = idx - tx4;
        float4 v = (j < CCH * CCH / 4) ? ((const float4*)Wg)[j]
                                       : ((const float4*)Wl)[j - CCH * CCH / 4];
        uint2 h, l;
        split4(v, h, l);
        ((uint2*)g_wh)[j] = h;
        ((uint2*)g_wl)[j] = l;
    }
}

// ---------------- merged dual GEMM via mma.sync bf16 (hi/lo, fp32 accum) ----
// 512 threads, block tile 128 rows x full K=128; warps 0-7 compute y (Wg),
// warps 8-15 compute h (Wl); A staged once in smem, single barrier.
#define WP 136                       // smem stride in bf16 (272 B): bank-clean
#define AARR (128 * WP * 2)          // bytes per smem array (34816)

__device__ __forceinline__ void mma_bf16(float* c, const unsigned* a, const unsigned* b) {
    asm volatile("mma.sync.aligned.m16n8k16.row.col.f32.bf16.bf16.f32 "
                 "{%0,%1,%2,%3}, {%4,%5,%6,%7}, {%8,%9}, {%0,%1,%2,%3};"
                 : "+f"(c[0]), "+f"(c[1]), "+f"(c[2]), "+f"(c[3])
                 : "r"(a[0]), "r"(a[1]), "r"(a[2]), "r"(a[3]),
                   "r"(b[0]), "r"(b[1]));
}

__global__ void __launch_bounds__(512, 1)
k_gemm(int n) {
    extern __shared__ char smc[];
    int tid = threadIdx.x;
    int row0 = blockIdx.x * 128;

    // stage A(hi,lo) + both W(hi,lo) pairs: 6 arrays x 128 rows x 16 uint4
    for (int i = tid; i < 6 * 2048; i += 512) {
        int a = i >> 11;
        int j = i & 2047;
        int r = j >> 4, q = j & 15;
        const __nv_bfloat16* srcp;
        switch (a) {
            case 0: { int rr = row0 + r; if (rr >= n) rr = n - 1;
                      srcp = g_xh + (size_t)rr * CCH; } break;
            case 1: { int rr = row0 + r; if (rr >= n) rr = n - 1;
                      srcp = g_xl + (size_t)rr * CCH; } break;
            case 2: srcp = g_wh + (size_t)r * CCH; break;
            case 3: srcp = g_wl + (size_t)r * CCH; break;
            case 4: srcp = g_wh + (size_t)(CCH + r) * CCH; break;
            default: srcp = g_wl + (size_t)(CCH + r) * CCH; break;
        }
        uint4 v = *(const uint4*)(srcp + q * 8);
        *(uint4*)(smc + a * AARR + ((size_t)r * WP + q * 8) * 2) = v;
    }
    __syncthreads();

    int wid = tid >> 5, lane = tid & 31;
    int g = wid >> 3, wl = wid & 7;
    int gq = lane >> 2, qq = lane & 3;
    int warpM = (wl & 3) * 32, warpN = (wl >> 2) * 64;
    const __nv_bfloat16* Ah = (const __nv_bfloat16*)(smc);
    const __nv_bfloat16* Al = (const __nv_bfloat16*)(smc + AARR);
    const __nv_bfloat16* Bh = (const __nv_bfloat16*)(smc + (2 + 2 * g) * AARR);
    const __nv_bfloat16* Bl = (const __nv_bfloat16*)(smc + (3 + 2 * g) * AARR);
    float* outp = g ? g_h : g_y;

    float acc[2][8][4];
    #pragma unroll
    for (int m = 0; m < 2; m++)
        #pragma unroll
        for (int j = 0; j < 8; j++)
            #pragma unroll
            for (int q = 0; q < 4; q++) acc[m][j][q] = 0.f;

    #pragma unroll
    for (int ks = 0; ks < 8; ks++) {
        int kb = ks * 16;
        unsigned ah[2][4], al[2][4];
        #pragma unroll
        for (int m = 0; m < 2; m++) {
            int rb = warpM + m * 16 + gq;
            int o0 = rb * WP + kb + qq * 2;
            int o1 = (rb + 8) * WP + kb + qq * 2;
            ah[m][0] = *(const unsigned*)(Ah + o0);
            ah[m][1] = *(const unsigned*)(Ah + o1);
            ah[m][2] = *(const unsigned*)(Ah + o0 + 8);
            ah[m][3] = *(const unsigned*)(Ah + o1 + 8);
            al[m][0] = *(const unsigned*)(Al + o0);
            al[m][1] = *(const unsigned*)(Al + o1);
            al[m][2] = *(const unsigned*)(Al + o0 + 8);
            al[m][3] = *(const unsigned*)(Al + o1 + 8);
        }
        #pragma unroll
        for (int j = 0; j < 8; j++) {
            int cbp = (warpN + j * 8 + gq) * WP + kb + qq * 2;
            unsigned bh[2], bl[2];
            bh[0] = *(const unsigned*)(Bh + cbp);
            bh[1] = *(const unsigned*)(Bh + cbp + 8);
            bl[0] = *(const unsigned*)(Bl + cbp);
            bl[1] = *(const unsigned*)(Bl + cbp + 8);
            mma_bf16(acc[0][j], ah[0], bh);
            mma_bf16(acc[1][j], ah[1], bh);
            mma_bf16(acc[0][j], al[0], bh);
            mma_bf16(acc[1][j], al[1], bh);
            mma_bf16(acc[0][j], ah[0], bl);
            mma_bf16(acc[1][j], ah[1], bl);
        }
    }

    #pragma unroll
    for (int m = 0; m < 2; m++) {
        int r = row0 + warpM + m * 16 + gq;
        #pragma unroll
        for (int j = 0; j < 8; j++) {
            int cc = warpN + j * 8 + qq * 2;
            if (r < n)
                *(float2*)(outp + (size_t)r * CCH + cc) =
                    make_float2(acc[m][j][0], acc[m][j][1]);
            if (r + 8 < n)
                *(float2*)(outp + (size_t)(r + 8) * CCH + cc) =
                    make_float2(acc[m][j][2], acc[m][j][3]);
        }
    }
}

// ---------------- fused edge attention + aggregation + BN partial stats -----
__device__ __forceinline__ float sigf(float v) { return 1.0f / (1.0f + __expf(-v)); }

__global__ void __launch_bounds__(256)
k_edge(const float* __restrict__ edge_attr,
       const int* __restrict__ ei, int n, int nE) {
    __shared__ float s_sum[CCH];
    __shared__ float s_sq[CCH];
    for (int i = threadIdx.x; i < CCH; i += 256) { s_sum[i] = 0.f; s_sq[i] = 0.f; }
    __syncthreads();

    int w    = (blockIdx.x * 256 + threadIdx.x) >> 5;
    int lane = threadIdx.x & 31;
    int cb   = lane * 4;

    if (w < n) {
        int deg = g_cnt[w];
        if (deg > SLOTS) deg = SLOTS;
        const int* sp  = g_slot + (size_t)w * SLOTS;
        const int* srp = g_src  + (size_t)w * SLOTS;
        float4 agg = make_float4(0.f, 0.f, 0.f, 0.f);
        float4 den = make_float4(0.f, 0.f, 0.f, 0.f);

        int p = 0;
        for (; p + 8 <= deg; p += 8) {
            int4 ea0 = *(const int4*)(sp + p),  ea1 = *(const int4*)(sp + p + 4);
            int4 sa0 = *(const int4*)(srp + p), sa1 = *(const int4*)(srp + p + 4);
            int es[8] = {ea0.x, ea0.y, ea0.z, ea0.w, ea1.x, ea1.y, ea1.z, ea1.w};
            int ss[8] = {sa0.x, sa0.y, sa0.z, sa0.w, sa1.x, sa1.y, sa1.z, sa1.w};
            float4 va[8], vy[8];
            #pragma unroll
            for (int j = 0; j < 8; j++) {
                va[j] = __ldcs((const float4*)(edge_attr + (size_t)es[j] * CCH + cb));
                vy[j] = *(const float4*)(g_y + (size_t)ss[j] * CCH + cb);
            }
            #pragma unroll
            for (int j = 0; j < 8; j++) {
                float gx = sigf(va[j].x), gy = sigf(va[j].y);
                float gz = sigf(va[j].z), gw = sigf(va[j].w);
                den.x += gx;  den.y += gy;  den.z += gz;  den.w += gw;
                agg.x = fmaf(gx, vy[j].x, agg.x);
                agg.y = fmaf(gy, vy[j].y, agg.y);
                agg.z = fmaf(gz, vy[j].z, agg.z);
                agg.w = fmaf(gw, vy[j].w, agg.w);
            }
        }
        for (; p < deg; p++) {
            int e0 = sp[p], s0 = srp[p];
            float4 va = __ldcs((const float4*)(edge_attr + (size_t)e0 * CCH + cb));
            float4 vy = *(const float4*)(g_y + (size_t)s0 * CCH + cb);
            float gx = sigf(va.x), gy = sigf(va.y), gz = sigf(va.z), gw = sigf(va.w);
            den.x += gx;  den.y += gy;  den.z += gz;  den.w += gw;
            agg.x = fmaf(gx, vy.x, agg.x);
            agg.y = fmaf(gy, vy.y, agg.y);
            agg.z = fmaf(gz, vy.z, agg.z);
            agg.w = fmaf(gw, vy.w, agg.w);
        }

        float4 hv = *(const float4*)(g_h + (size_t)w * CCH + cb);
        float4 h;
        h.x = hv.x + agg.x / (den.x + 1e-8f);
        h.y = hv.y + agg.y / (den.y + 1e-8f);
        h.z = hv.z + agg.z / (den.z + 1e-8f);
        h.w = hv.w + agg.w / (den.w + 1e-8f);
        *(float4*)(g_h + (size_t)w * CCH + cb) = h;

        atomicAdd(&s_sum[cb + 0], h.x);  atomicAdd(&s_sq[cb + 0], h.x * h.x);
        atomicAdd(&s_sum[cb + 1], h.y);  atomicAdd(&s_sq[cb + 1], h.y * h.y);
        atomicAdd(&s_sum[cb + 2], h.z);  atomicAdd(&s_sq[cb + 2], h.z * h.z);
        atomicAdd(&s_sum[cb + 3], h.w);  atomicAdd(&s_sq[cb + 3], h.w * h.w);
    }
    __syncthreads();
    if (threadIdx.x < CCH) {
        atomicAdd(&g_sum[threadIdx.x],   s_sum[threadIdx.x]);
        atomicAdd(&g_sumsq[threadIdx.x], s_sq[threadIdx.x]);
    }
}

// ---------------- epilogue with fused BN finalize ----------------
__global__ void k_out(const float* __restrict__ x,
                      const float* __restrict__ gamma,
                      const float* __restrict__ beta,
                      float* __restrict__ out, int n) {
    __shared__ float ss[CCH], sh[CCH];
    if (threadIdx.x < CCH) {
        int c = threadIdx.x;
        float invn = 1.0f / (float)n;
        float mean = g_sum[c] * invn;
        float var  = g_sumsq[c] * invn - mean * mean;
        float istd = rsqrtf(var + 1e-5f);
        float sc = istd * gamma[c];
        ss[c] = sc;
        sh[c] = beta[c] - mean * sc;
    }
    __syncthreads();
    int idx = blockIdx.x * blockDim.x + threadIdx.x;
    int total = n * (CCH / 4);
    if (idx < total) {
        int cb = (idx & (CCH / 4 - 1)) * 4;
        float4 xv = ((const float4*)x)[idx];
        float4 hv = ((const float4*)g_h)[idx];
        float4 o;
        o.x = xv.x + fmaxf(fmaf(hv.x, ss[cb + 0], sh[cb + 0]), 0.f);
        o.y = xv.y + fmaxf(fmaf(hv.y, ss[cb + 1], sh[cb + 1]), 0.f);
        o.z = xv.z + fmaxf(fmaf(hv.z, ss[cb + 2], sh[cb + 2]), 0.f);
        o.w = xv.w + fmaxf(fmaf(hv.w, ss[cb + 3], sh[cb + 3]), 0.f);
        ((float4*)out)[idx] = o;
    }
}

// ---------------- launch ----------------
extern "C" void kernel_launch(void* const* d_in, const int* in_sizes, int n_in,
                              void* d_out, int out_size) {
    const float* x     = (const float*)d_in[0];
    const float* ea    = (const float*)d_in[1];
    const int*   ei    = (const int*)d_in[2];
    const float* Wg    = (const float*)d_in[3];
    const float* Wl    = (const float*)d_in[4];
    const float* gamma = (const float*)d_in[5];
    const float* beta  = (const float*)d_in[6];
    float* out = (float*)d_out;

    int n  = in_sizes[0] / CCH;
    int nE = in_sizes[2] / 2;
    int nb = (n + 127) / 128;
    int smem = 6 * AARR;    // 208896 B

    cudaFuncSetAttribute(k_gemm, cudaFuncAttributeMaxDynamicSharedMemorySize, smem);

    static cudaStream_t s2 = nullptr;
    static cudaEvent_t ev0 = nullptr, ev1 = nullptr;
    if (s2 == nullptr) {
        cudaStreamCreate(&s2);
        cudaEventCreateWithFlags(&ev0, cudaEventDisableTiming);
        cudaEventCreateWithFlags(&ev1, cudaEventDisableTiming);
    }

    // fork: bucket build on s2, convert+GEMM on legacy stream
    cudaEventRecord(ev0, 0);
    cudaStreamWaitEvent(s2, ev0, 0);

    k_zero<<<(n + 255) / 256, 256, 0, s2>>>(n);
    k_bucket<<<(nE + 255) / 256, 256, 0, s2>>>(ei, nE, n);
    cudaEventRecord(ev1, s2);

    int cvt_items = n * (CCH / 4) + 2 * CCH * CCH / 4;
    k_cvt<<<(cvt_items + 255) / 256, 256>>>(x, Wg, Wl, n);
    k_gemm<<<nb, 512, smem>>>(n);

    cudaStreamWaitEvent(0, ev1, 0);
    k_edge<<<(n * 32 + 255) / 256, 256>>>(ea, ei, n, nE);
    k_out<<<(n * (CCH / 4) + 255) / 256, 256>>>(x, gamma, beta, out, n);
}

// round 11
// speedup vs baseline: 1.4720x; 1.4720x over previous
#include <cuda_runtime.h>
#include <cuda_bf16.h>
#include <cstddef>
#include <cstdint>

#define NMAX 50000
#define EMAX 600000
#define CCH 128
#define SLOTS 64
#define WP 40   // smem stride in bf16 (80B) - conflict-free fragment LDS

// ---------------- scratch (static device globals; no allocation) -------------
__device__ float g_y[(size_t)NMAX * CCH];
__device__ float g_h[(size_t)NMAX * CCH];
__device__ int   g_cnt[NMAX];
__device__ int   g_slot[(size_t)NMAX * SLOTS];
__device__ int   g_src[(size_t)NMAX * SLOTS];
__device__ float g_sum[CCH];
__device__ float g_sumsq[CCH];

// ---------------- zero per-launch state ----------------
__global__ void k_zero(int n) {
    int i = blockIdx.x * blockDim.x + threadIdx.x;
    if (i < n) g_cnt[i] = 0;
    if (i < CCH) { g_sum[i] = 0.f; g_sumsq[i] = 0.f; }
}

// ---------------- bucket fill (slot = edge id, src prevalidated) -------------
__global__ void k_bucket(const int* __restrict__ ei, int nE, int n) {
    int e = blockIdx.x * blockDim.x + threadIdx.x;
    if (e < nE) {
        int t = ei[nE + e];                       // row 1 = target
        if ((unsigned)t < (unsigned)n) {
            int p = atomicAdd(&g_cnt[t], 1);
            if (p < SLOTS) {
                int s = ei[e];                    // row 0 = source
                if ((unsigned)s >= (unsigned)n) s = 0;
                g_slot[(size_t)t * SLOTS + p] = e;
                g_src [(size_t)t * SLOTS + p] = s;
            }
        }
    }
}

// ---------------- bf16 hi/lo split ----------------
__device__ __forceinline__ void split4(float4 v, uint2& h, uint2& l) {
    __nv_bfloat16 hx = __float2bfloat16(v.x);
    __nv_bfloat16 hy = __float2bfloat16(v.y);
    __nv_bfloat16 hz = __float2bfloat16(v.z);
    __nv_bfloat16 hw = __float2bfloat16(v.w);
    __nv_bfloat16 lx = __float2bfloat16(v.x - __bfloat162float(hx));
    __nv_bfloat16 ly = __float2bfloat16(v.y - __bfloat162float(hy));
    __nv_bfloat16 lz = __float2bfloat16(v.z - __bfloat162float(hz));
    __nv_bfloat16 lw = __float2bfloat16(v.w - __bfloat162float(hw));
    h.x = ((unsigned)__bfloat16_as_ushort(hy) << 16) | __bfloat16_as_ushort(hx);
    h.y = ((unsigned)__bfloat16_as_ushort(hw) << 16) | __bfloat16_as_ushort(hz);
    l.x = ((unsigned)__bfloat16_as_ushort(ly) << 16) | __bfloat16_as_ushort(lx);
    l.y = ((unsigned)__bfloat16_as_ushort(lw) << 16) | __bfloat16_as_ushort(lz);
}

// ---------------- dual GEMM via mma.sync bf16 (hi/lo split, fp32 accum) -----
// grid = 2*nb: bid<nb -> y = x@Wg^T, else h = x@Wl^T.
// 256 threads, block tile 128x128, K in 4 panels of 32; inline fp32->bf16
// hi/lo conversion while staging smem (no separate convert kernel).
__device__ __forceinline__ void mma_bf16(float* c, const unsigned* a, const unsigned* b) {
    asm volatile("mma.sync.aligned.m16n8k16.row.col.f32.bf16.bf16.f32 "
                 "{%0,%1,%2,%3}, {%4,%5,%6,%7}, {%8,%9}, {%0,%1,%2,%3};"
                 : "+f"(c[0]), "+f"(c[1]), "+f"(c[2]), "+f"(c[3])
                 : "r"(a[0]), "r"(a[1]), "r"(a[2]), "r"(a[3]),
                   "r"(b[0]), "r"(b[1]));
}

__global__ void __launch_bounds__(256, 2)
k_gemm(const float* __restrict__ x,
       const float* __restrict__ Wg,
       const float* __restrict__ Wl,
       int n, int nb) {
    __shared__ __nv_bfloat16 Ah[128 * WP], Al[128 * WP];
    __shared__ __nv_bfloat16 Bh[128 * WP], Bl[128 * WP];
    int tid = threadIdx.x;
    int pass = (blockIdx.x >= nb) ? 1 : 0;
    int row0 = (pass ? (blockIdx.x - nb) : blockIdx.x) * 128;
    const float* Wp = pass ? Wl : Wg;
    float* outp = pass ? g_h : g_y;
    int wid = tid >> 5, lane = tid & 31;
    int gq = lane >> 2, qq = lane & 3;
    int warpM = (wid & 3) * 32, warpN = (wid >> 2) * 64;

    float acc[2][8][4];
    #pragma unroll
    for (int m = 0; m < 2; m++)
        #pragma unroll
        for (int j = 0; j < 8; j++)
            #pragma unroll
            for (int q = 0; q < 4; q++) acc[m][j][q] = 0.f;

    for (int p = 0; p < 4; p++) {
        int k0 = p * 32;
        __syncthreads();
        for (int i = tid; i < 1024; i += 256) {
            int r = i >> 3, q = i & 7;
            int rr = row0 + r; if (rr >= n) rr = n - 1;
            float4 xv = *(const float4*)(x + (size_t)rr * CCH + k0 + q * 4);
            uint2 h, l;
            split4(xv, h, l);
            *(uint2*)(Ah + r * WP + q * 4) = h;
            *(uint2*)(Al + r * WP + q * 4) = l;
            float4 wv = *(const float4*)(Wp + (size_t)r * CCH + k0 + q * 4);
            split4(wv, h, l);
            *(uint2*)(Bh + r * WP + q * 4) = h;
            *(uint2*)(Bl + r * WP + q * 4) = l;
        }
        __syncthreads();

        #pragma unroll
        for (int ks = 0; ks < 2; ks++) {
            int kb = ks * 16;
            unsigned ah[2][4], al[2][4];
            #pragma unroll
            for (int m = 0; m < 2; m++) {
                int rb = warpM + m * 16 + gq;
                int o0 = rb * WP + kb + qq * 2;
                int o1 = (rb + 8) * WP + kb + qq * 2;
                ah[m][0] = *(const unsigned*)(Ah + o0);
                ah[m][1] = *(const unsigned*)(Ah + o1);
                ah[m][2] = *(const unsigned*)(Ah + o0 + 8);
                ah[m][3] = *(const unsigned*)(Ah + o1 + 8);
                al[m][0] = *(const unsigned*)(Al + o0);
                al[m][1] = *(const unsigned*)(Al + o1);
                al[m][2] = *(const unsigned*)(Al + o0 + 8);
                al[m][3] = *(const unsigned*)(Al + o1 + 8);
            }
            #pragma unroll
            for (int j = 0; j < 8; j++) {
                int cbp = (warpN + j * 8 + gq) * WP + kb + qq * 2;
                unsigned bh[2], bl[2];
                bh[0] = *(const unsigned*)(Bh + cbp);
                bh[1] = *(const unsigned*)(Bh + cbp + 8);
                bl[0] = *(const unsigned*)(Bl + cbp);
                bl[1] = *(const unsigned*)(Bl + cbp + 8);
                mma_bf16(acc[0][j], ah[0], bh);
                mma_bf16(acc[1][j], ah[1], bh);
                mma_bf16(acc[0][j], al[0], bh);
                mma_bf16(acc[1][j], al[1], bh);
                mma_bf16(acc[0][j], ah[0], bl);
                mma_bf16(acc[1][j], ah[1], bl);
            }
        }
    }

    #pragma unroll
    for (int m = 0; m < 2; m++) {
        int r = row0 + warpM + m * 16 + gq;
        #pragma unroll
        for (int j = 0; j < 8; j++) {
            int cc = warpN + j * 8 + qq * 2;
            if (r < n)
                *(float2*)(outp + (size_t)r * CCH + cc) =
                    make_float2(acc[m][j][0], acc[m][j][1]);
            if (r + 8 < n)
                *(float2*)(outp + (size_t)(r + 8) * CCH + cc) =
                    make_float2(acc[m][j][2], acc[m][j][3]);
        }
    }
}

// ---------------- fused edge attention + aggregation + BN partial stats -----
__device__ __forceinline__ float sigf(float v) { return 1.0f / (1.0f + __expf(-v)); }

__global__ void __launch_bounds__(256)
k_edge(const float* __restrict__ edge_attr,
       const int* __restrict__ ei, int n, int nE) {
    __shared__ float s_sum[CCH];
    __shared__ float s_sq[CCH];
    for (int i = threadIdx.x; i < CCH; i += 256) { s_sum[i] = 0.f; s_sq[i] = 0.f; }
    __syncthreads();

    int w    = (blockIdx.x * 256 + threadIdx.x) >> 5;
    int lane = threadIdx.x & 31;
    int cb   = lane * 4;

    if (w < n) {
        int deg = g_cnt[w];
        if (deg > SLOTS) deg = SLOTS;
        const int* sp  = g_slot + (size_t)w * SLOTS;
        const int* srp = g_src  + (size_t)w * SLOTS;
        float4 agg = make_float4(0.f, 0.f, 0.f, 0.f);
        float4 den = make_float4(0.f, 0.f, 0.f, 0.f);

        int p = 0;
        for (; p + 4 <= deg; p += 4) {
            int4 es = *(const int4*)(sp + p);
            int4 ss = *(const int4*)(srp + p);
            float4 va0 = __ldcs((const float4*)(edge_attr + (size_t)es.x * CCH + cb));
            float4 va1 = __ldcs((const float4*)(edge_attr + (size_t)es.y * CCH + cb));
            float4 va2 = __ldcs((const float4*)(edge_attr + (size_t)es.z * CCH + cb));
            float4 va3 = __ldcs((const float4*)(edge_attr + (size_t)es.w * CCH + cb));
            float4 vy0 = *(const float4*)(g_y + (size_t)ss.x * CCH + cb);
            float4 vy1 = *(const float4*)(g_y + (size_t)ss.y * CCH + cb);
            float4 vy2 = *(const float4*)(g_y + (size_t)ss.z * CCH + cb);
            float4 vy3 = *(const float4*)(g_y + (size_t)ss.w * CCH + cb);
            float g0, g1, g2, g3;
            g0 = sigf(va0.x); g1 = sigf(va1.x); g2 = sigf(va2.x); g3 = sigf(va3.x);
            den.x += (g0 + g1) + (g2 + g3);
            agg.x = fmaf(g0, vy0.x, fmaf(g1, vy1.x, fmaf(g2, vy2.x, fmaf(g3, vy3.x, agg.x))));
            g0 = sigf(va0.y); g1 = sigf(va1.y); g2 = sigf(va2.y); g3 = sigf(va3.y);
            den.y += (g0 + g1) + (g2 + g3);
            agg.y = fmaf(g0, vy0.y, fmaf(g1, vy1.y, fmaf(g2, vy2.y, fmaf(g3, vy3.y, agg.y))));
            g0 = sigf(va0.z); g1 = sigf(va1.z); g2 = sigf(va2.z); g3 = sigf(va3.z);
            den.z += (g0 + g1) + (g2 + g3);
            agg.z = fmaf(g0, vy0.z, fmaf(g1, vy1.z, fmaf(g2, vy2.z, fmaf(g3, vy3.z, agg.z))));
            g0 = sigf(va0.w); g1 = sigf(va1.w); g2 = sigf(va2.w); g3 = sigf(va3.w);
            den.w += (g0 + g1) + (g2 + g3);
            agg.w = fmaf(g0, vy0.w, fmaf(g1, vy1.w, fmaf(g2, vy2.w, fmaf(g3, vy3.w, agg.w))));
        }
        for (; p < deg; p++) {
            int e0 = sp[p], s0 = srp[p];
            float4 va = __ldcs((const float4*)(edge_attr + (size_t)e0 * CCH + cb));
            float4 vy = *(const float4*)(g_y + (size_t)s0 * CCH + cb);
            float gx = sigf(va.x), gy = sigf(va.y), gz = sigf(va.z), gw = sigf(va.w);
            den.x += gx;  den.y += gy;  den.z += gz;  den.w += gw;
            agg.x = fmaf(gx, vy.x, agg.x);
            agg.y = fmaf(gy, vy.y, agg.y);
            agg.z = fmaf(gz, vy.z, agg.z);
            agg.w = fmaf(gw, vy.w, agg.w);
        }

        float4 hv = *(const float4*)(g_h + (size_t)w * CCH + cb);
        float4 h;
        h.x = hv.x + agg.x / (den.x + 1e-8f);
        h.y = hv.y + agg.y / (den.y + 1e-8f);
        h.z = hv.z + agg.z / (den.z + 1e-8f);
        h.w = hv.w + agg.w / (den.w + 1e-8f);
        *(float4*)(g_h + (size_t)w * CCH + cb) = h;

        atomicAdd(&s_sum[cb + 0], h.x);  atomicAdd(&s_sq[cb + 0], h.x * h.x);
        atomicAdd(&s_sum[cb + 1], h.y);  atomicAdd(&s_sq[cb + 1], h.y * h.y);
        atomicAdd(&s_sum[cb + 2], h.z);  atomicAdd(&s_sq[cb + 2], h.z * h.z);
        atomicAdd(&s_sum[cb + 3], h.w);  atomicAdd(&s_sq[cb + 3], h.w * h.w);
    }
    __syncthreads();
    if (threadIdx.x < CCH) {
        atomicAdd(&g_sum[threadIdx.x],   s_sum[threadIdx.x]);
        atomicAdd(&g_sumsq[threadIdx.x], s_sq[threadIdx.x]);
    }
}

// ---------------- epilogue with fused BN finalize ----------------
__global__ void k_out(const float* __restrict__ x,
                      const float* __restrict__ gamma,
                      const float* __restrict__ beta,
                      float* __restrict__ out, int n) {
    __shared__ float ss[CCH], sh[CCH];
    if (threadIdx.x < CCH) {
        int c = threadIdx.x;
        float invn = 1.0f / (float)n;
        float mean = g_sum[c] * invn;
        float var  = g_sumsq[c] * invn - mean * mean;
        float istd = rsqrtf(var + 1e-5f);
        float sc = istd * gamma[c];
        ss[c] = sc;
        sh[c] = beta[c] - mean * sc;
    }
    __syncthreads();
    int idx = blockIdx.x * blockDim.x + threadIdx.x;
    int total = n * (CCH / 4);
    if (idx < total) {
        int cb = (idx & (CCH / 4 - 1)) * 4;
        float4 xv = ((const float4*)x)[idx];
        float4 hv = ((const float4*)g_h)[idx];
        float4 o;
        o.x = xv.x + fmaxf(fmaf(hv.x, ss[cb + 0], sh[cb + 0]), 0.f);
        o.y = xv.y + fmaxf(fmaf(hv.y, ss[cb + 1], sh[cb + 1]), 0.f);
        o.z = xv.z + fmaxf(fmaf(hv.z, ss[cb + 2], sh[cb + 2]), 0.f);
        o.w = xv.w + fmaxf(fmaf(hv.w, ss[cb + 3], sh[cb + 3]), 0.f);
        ((float4*)out)[idx] = o;
    }
}

// ---------------- launch ----------------
extern "C" void kernel_launch(void* const* d_in, const int* in_sizes, int n_in,
                              void* d_out, int out_size) {
    const float* x     = (const float*)d_in[0];
    const float* ea    = (const float*)d_in[1];
    const int*   ei    = (const int*)d_in[2];
    const float* Wg    = (const float*)d_in[3];
    const float* Wl    = (const float*)d_in[4];
    const float* gamma = (const float*)d_in[5];
    const float* beta  = (const float*)d_in[6];
    float* out = (float*)d_out;

    int n  = in_sizes[0] / CCH;
    int nE = in_sizes[2] / 2;
    int nb = (n + 127) / 128;

    static cudaStream_t s2 = nullptr;
    static cudaEvent_t ev0 = nullptr, ev1 = nullptr;
    if (s2 == nullptr) {
        cudaStreamCreate(&s2);
        cudaEventCreateWithFlags(&ev0, cudaEventDisableTiming);
        cudaEventCreateWithFlags(&ev1, cudaEventDisableTiming);
    }

    // fork: bucket build on s2, GEMM on legacy stream
    cudaEventRecord(ev0, 0);
    cudaStreamWaitEvent(s2, ev0, 0);

    k_zero<<<(n + 255) / 256, 256, 0, s2>>>(n);
    k_bucket<<<(nE + 255) / 256, 256, 0, s2>>>(ei, nE, n);
    cudaEventRecord(ev1, s2);

    k_gemm<<<2 * nb, 256>>>(x, Wg, Wl, n, nb);

    cudaStreamWaitEvent(0, ev1, 0);
    k_edge<<<(n * 32 + 255) / 256, 256>>>(ea, ei, n, nE);
    k_out<<<(n * (CCH / 4) + 255) / 256, 256>>>(x, gamma, beta, out, n);
}

// round 14
// speedup vs baseline: 1.4831x; 1.0076x over previous
#include <cuda_runtime.h>
#include <cuda_bf16.h>
#include <cstddef>
#include <cstdint>

#define NMAX 50000
#define EMAX 600000
#define CCH 128
#define SLOTS 64
#define WP 40   // smem stride in bf16 (80B) - conflict-free fragment LDS

// ---------------- scratch (static device globals; no allocation) -------------
__device__ float g_y[(size_t)NMAX * CCH];
__device__ float g_h[(size_t)NMAX * CCH];
__device__ int   g_cnt[NMAX];
__device__ int   g_slot[(size_t)NMAX * SLOTS];
__device__ int   g_src[(size_t)NMAX * SLOTS];
__device__ float g_sum[CCH];
__device__ float g_sumsq[CCH];

// ---------------- zero per-launch state ----------------
__global__ void k_zero(int n) {
    int i = blockIdx.x * blockDim.x + threadIdx.x;
    if (i < n) g_cnt[i] = 0;
    if (i < CCH) { g_sum[i] = 0.f; g_sumsq[i] = 0.f; }
}

// ---------------- bucket fill (slot = edge id, src prevalidated) -------------
__global__ void k_bucket(const int* __restrict__ ei, int nE, int n) {
    int e = blockIdx.x * blockDim.x + threadIdx.x;
    if (e < nE) {
        int t = ei[nE + e];                       // row 1 = target
        if ((unsigned)t < (unsigned)n) {
            int p = atomicAdd(&g_cnt[t], 1);
            if (p < SLOTS) {
                int s = ei[e];                    // row 0 = source
                if ((unsigned)s >= (unsigned)n) s = 0;
                g_slot[(size_t)t * SLOTS + p] = e;
                g_src [(size_t)t * SLOTS + p] = s;
            }
        }
    }
}

// ---------------- bf16 hi/lo split ----------------
__device__ __forceinline__ void split4(float4 v, uint2& h, uint2& l) {
    __nv_bfloat16 hx = __float2bfloat16(v.x);
    __nv_bfloat16 hy = __float2bfloat16(v.y);
    __nv_bfloat16 hz = __float2bfloat16(v.z);
    __nv_bfloat16 hw = __float2bfloat16(v.w);
    __nv_bfloat16 lx = __float2bfloat16(v.x - __bfloat162float(hx));
    __nv_bfloat16 ly = __float2bfloat16(v.y - __bfloat162float(hy));
    __nv_bfloat16 lz = __float2bfloat16(v.z - __bfloat162float(hz));
    __nv_bfloat16 lw = __float2bfloat16(v.w - __bfloat162float(hw));
    h.x = ((unsigned)__bfloat16_as_ushort(hy) << 16) | __bfloat16_as_ushort(hx);
    h.y = ((unsigned)__bfloat16_as_ushort(hw) << 16) | __bfloat16_as_ushort(hz);
    l.x = ((unsigned)__bfloat16_as_ushort(ly) << 16) | __bfloat16_as_ushort(lx);
    l.y = ((unsigned)__bfloat16_as_ushort(lw) << 16) | __bfloat16_as_ushort(lz);
}

// ---------------- dual GEMM via mma.sync bf16 (hi/lo split, fp32 accum) -----
__device__ __forceinline__ void mma_bf16(float* c, const unsigned* a, const unsigned* b) {
    asm volatile("mma.sync.aligned.m16n8k16.row.col.f32.bf16.bf16.f32 "
                 "{%0,%1,%2,%3}, {%4,%5,%6,%7}, {%8,%9}, {%0,%1,%2,%3};"
                 : "+f"(c[0]), "+f"(c[1]), "+f"(c[2]), "+f"(c[3])
                 : "r"(a[0]), "r"(a[1]), "r"(a[2]), "r"(a[3]),
                   "r"(b[0]), "r"(b[1]));
}

__global__ void __launch_bounds__(256, 2)
k_gemm(const float* __restrict__ x,
       const float* __restrict__ Wg,
       const float* __restrict__ Wl,
       int n, int nb) {
    __shared__ __nv_bfloat16 Ah[128 * WP], Al[128 * WP];
    __shared__ __nv_bfloat16 Bh[128 * WP], Bl[128 * WP];
    int tid = threadIdx.x;
    int pass = (blockIdx.x >= nb) ? 1 : 0;
    int row0 = (pass ? (blockIdx.x - nb) : blockIdx.x) * 128;
    const float* Wp = pass ? Wl : Wg;
    float* outp = pass ? g_h : g_y;
    int wid = tid >> 5, lane = tid & 31;
    int gq = lane >> 2, qq = lane & 3;
    int warpM = (wid & 3) * 32, warpN = (wid >> 2) * 64;

    float acc[2][8][4];
    #pragma unroll
    for (int m = 0; m < 2; m++)
        #pragma unroll
        for (int j = 0; j < 8; j++)
            #pragma unroll
            for (int q = 0; q < 4; q++) acc[m][j][q] = 0.f;

    for (int p = 0; p < 4; p++) {
        int k0 = p * 32;
        __syncthreads();
        for (int i = tid; i < 1024; i += 256) {
            int r = i >> 3, q = i & 7;
            int rr = row0 + r; if (rr >= n) rr = n - 1;
            float4 xv = *(const float4*)(x + (size_t)rr * CCH + k0 + q * 4);
            uint2 h, l;
            split4(xv, h, l);
            *(uint2*)(Ah + r * WP + q * 4) = h;
            *(uint2*)(Al + r * WP + q * 4) = l;
            float4 wv = *(const float4*)(Wp + (size_t)r * CCH + k0 + q * 4);
            split4(wv, h, l);
            *(uint2*)(Bh + r * WP + q * 4) = h;
            *(uint2*)(Bl + r * WP + q * 4) = l;
        }
        __syncthreads();

        #pragma unroll
        for (int ks = 0; ks < 2; ks++) {
            int kb = ks * 16;
            unsigned ah[2][4], al[2][4];
            #pragma unroll
            for (int m = 0; m < 2; m++) {
                int rb = warpM + m * 16 + gq;
                int o0 = rb * WP + kb + qq * 2;
                int o1 = (rb + 8) * WP + kb + qq * 2;
                ah[m][0] = *(const unsigned*)(Ah + o0);
                ah[m][1] = *(const unsigned*)(Ah + o1);
                ah[m][2] = *(const unsigned*)(Ah + o0 + 8);
                ah[m][3] = *(const unsigned*)(Ah + o1 + 8);
                al[m][0] = *(const unsigned*)(Al + o0);
                al[m][1] = *(const unsigned*)(Al + o1);
                al[m][2] = *(const unsigned*)(Al + o0 + 8);
                al[m][3] = *(const unsigned*)(Al + o1 + 8);
            }
            #pragma unroll
            for (int j = 0; j < 8; j++) {
                int cbp = (warpN + j * 8 + gq) * WP + kb + qq * 2;
                unsigned bh[2], bl[2];
                bh[0] = *(const unsigned*)(Bh + cbp);
                bh[1] = *(const unsigned*)(Bh + cbp + 8);
                bl[0] = *(const unsigned*)(Bl + cbp);
                bl[1] = *(const unsigned*)(Bl + cbp + 8);
                mma_bf16(acc[0][j], ah[0], bh);
                mma_bf16(acc[1][j], ah[1], bh);
                mma_bf16(acc[0][j], al[0], bh);
                mma_bf16(acc[1][j], al[1], bh);
                mma_bf16(acc[0][j], ah[0], bl);
                mma_bf16(acc[1][j], ah[1], bl);
            }
        }
    }

    #pragma unroll
    for (int m = 0; m < 2; m++) {
        int r = row0 + warpM + m * 16 + gq;
        #pragma unroll
        for (int j = 0; j < 8; j++) {
            int cc = warpN + j * 8 + qq * 2;
            if (r < n)
                *(float2*)(outp + (size_t)r * CCH + cc) =
                    make_float2(acc[m][j][0], acc[m][j][1]);
            if (r + 8 < n)
                *(float2*)(outp + (size_t)(r + 8) * CCH + cc) =
                    make_float2(acc[m][j][2], acc[m][j][3]);
        }
    }
}

// ---------------- fused edge attention + aggregation + BN partial stats -----
// Two warps per node: warp A takes edges [0,mid), warp B [mid,deg) with the
// split point rounded UP to a multiple of 4 so both int4 batch loops start
// 16B-aligned. Partials combined through smem.
__device__ __forceinline__ float sigf(float v) {
    return __fdividef(1.0f, 1.0f + __expf(-v));
}

__global__ void __launch_bounds__(256)
k_edge(const float* __restrict__ edge_attr, int n) {
    __shared__ float s_sum[CCH];
    __shared__ float s_sq[CCH];
    __shared__ float4 sAgg[8][32];
    __shared__ float4 sDen[8][32];
    for (int i = threadIdx.x; i < CCH; i += 256) { s_sum[i] = 0.f; s_sq[i] = 0.f; }

    int wid  = threadIdx.x >> 5;
    int lane = threadIdx.x & 31;
    int node = blockIdx.x * 4 + (wid >> 1);
    int half = wid & 1;
    int cb   = lane * 4;

    float4 agg = make_float4(0.f, 0.f, 0.f, 0.f);
    float4 den = make_float4(0.f, 0.f, 0.f, 0.f);

    if (node < n) {
        int deg = g_cnt[node];
        if (deg > SLOTS) deg = SLOTS;
        int mid = ((deg >> 1) + 3) & ~3;          // 4-aligned split point
        if (mid > deg) mid = deg;
        int p0 = half ? mid : 0;
        int p1 = half ? deg : mid;
        const int* sp  = g_slot + (size_t)node * SLOTS;
        const int* srp = g_src  + (size_t)node * SLOTS;

        int p = p0;
        for (; p + 4 <= p1; p += 4) {
            int4 es = *(const int4*)(sp + p);
            int4 ss = *(const int4*)(srp + p);
            float4 va0 = __ldcs((const float4*)(edge_attr + (size_t)es.x * CCH + cb));
            float4 va1 = __ldcs((const float4*)(edge_attr + (size_t)es.y * CCH + cb));
            float4 va2 = __ldcs((const float4*)(edge_attr + (size_t)es.z * CCH + cb));
            float4 va3 = __ldcs((const float4*)(edge_attr + (size_t)es.w * CCH + cb));
            float4 vy0 = *(const float4*)(g_y + (size_t)ss.x * CCH + cb);
            float4 vy1 = *(const float4*)(g_y + (size_t)ss.y * CCH + cb);
            float4 vy2 = *(const float4*)(g_y + (size_t)ss.z * CCH + cb);
            float4 vy3 = *(const float4*)(g_y + (size_t)ss.w * CCH + cb);
            float g0, g1, g2, g3;
            g0 = sigf(va0.x); g1 = sigf(va1.x); g2 = sigf(va2.x); g3 = sigf(va3.x);
            den.x += (g0 + g1) + (g2 + g3);
            agg.x = fmaf(g0, vy0.x, fmaf(g1, vy1.x, fmaf(g2, vy2.x, fmaf(g3, vy3.x, agg.x))));
            g0 = sigf(va0.y); g1 = sigf(va1.y); g2 = sigf(va2.y); g3 = sigf(va3.y);
            den.y += (g0 + g1) + (g2 + g3);
            agg.y = fmaf(g0, vy0.y, fmaf(g1, vy1.y, fmaf(g2, vy2.y, fmaf(g3, vy3.y, agg.y))));
            g0 = sigf(va0.z); g1 = sigf(va1.z); g2 = sigf(va2.z); g3 = sigf(va3.z);
            den.z += (g0 + g1) + (g2 + g3);
            agg.z = fmaf(g0, vy0.z, fmaf(g1, vy1.z, fmaf(g2, vy2.z, fmaf(g3, vy3.z, agg.z))));
            g0 = sigf(va0.w); g1 = sigf(va1.w); g2 = sigf(va2.w); g3 = sigf(va3.w);
            den.w += (g0 + g1) + (g2 + g3);
            agg.w = fmaf(g0, vy0.w, fmaf(g1, vy1.w, fmaf(g2, vy2.w, fmaf(g3, vy3.w, agg.w))));
        }
        for (; p < p1; p++) {
            int e0 = sp[p], s0 = srp[p];
            float4 va = __ldcs((const float4*)(edge_attr + (size_t)e0 * CCH + cb));
            float4 vy = *(const float4*)(g_y + (size_t)s0 * CCH + cb);
            float gx = sigf(va.x), gy = sigf(va.y), gz = sigf(va.z), gw = sigf(va.w);
            den.x += gx;  den.y += gy;  den.z += gz;  den.w += gw;
            agg.x = fmaf(gx, vy.x, agg.x);
            agg.y = fmaf(gy, vy.y, agg.y);
            agg.z = fmaf(gz, vy.z, agg.z);
            agg.w = fmaf(gw, vy.w, agg.w);
        }
    }

    sAgg[wid][lane] = agg;
    sDen[wid][lane] = den;
    __syncthreads();

    if (node < n && half == 0) {
        float4 a2 = sAgg[wid + 1][lane];
        float4 d2 = sDen[wid + 1][lane];
        agg.x += a2.x;  agg.y += a2.y;  agg.z += a2.z;  agg.w += a2.w;
        den.x += d2.x;  den.y += d2.y;  den.z += d2.z;  den.w += d2.w;

        float4 hv = *(const float4*)(g_h + (size_t)node * CCH + cb);
        float4 h;
        h.x = hv.x + agg.x / (den.x + 1e-8f);
        h.y = hv.y + agg.y / (den.y + 1e-8f);
        h.z = hv.z + agg.z / (den.z + 1e-8f);
        h.w = hv.w + agg.w / (den.w + 1e-8f);
        *(float4*)(g_h + (size_t)node * CCH + cb) = h;

        atomicAdd(&s_sum[cb + 0], h.x);  atomicAdd(&s_sq[cb + 0], h.x * h.x);
        atomicAdd(&s_sum[cb + 1], h.y);  atomicAdd(&s_sq[cb + 1], h.y * h.y);
        atomicAdd(&s_sum[cb + 2], h.z);  atomicAdd(&s_sq[cb + 2], h.z * h.z);
        atomicAdd(&s_sum[cb + 3], h.w);  atomicAdd(&s_sq[cb + 3], h.w * h.w);
    }
    __syncthreads();
    if (threadIdx.x < CCH) {
        atomicAdd(&g_sum[threadIdx.x],   s_sum[threadIdx.x]);
        atomicAdd(&g_sumsq[threadIdx.x], s_sq[threadIdx.x]);
    }
}

// ---------------- epilogue with fused BN finalize ----------------
__global__ void k_out(const float* __restrict__ x,
                      const float* __restrict__ gamma,
                      const float* __restrict__ beta,
                      float* __restrict__ out, int n) {
    __shared__ float ss[CCH], sh[CCH];
    if (threadIdx.x < CCH) {
        int c = threadIdx.x;
        float invn = 1.0f / (float)n;
        float mean = g_sum[c] * invn;
        float var  = g_sumsq[c] * invn - mean * mean;
        float istd = rsqrtf(var + 1e-5f);
        float sc = istd * gamma[c];
        ss[c] = sc;
        sh[c] = beta[c] - mean * sc;
    }
    __syncthreads();
    int idx = blockIdx.x * blockDim.x + threadIdx.x;
    int total = n * (CCH / 4);
    if (idx < total) {
        int cb = (idx & (CCH / 4 - 1)) * 4;
        float4 xv = ((const float4*)x)[idx];
        float4 hv = ((const float4*)g_h)[idx];
        float4 o;
        o.x = xv.x + fmaxf(fmaf(hv.x, ss[cb + 0], sh[cb + 0]), 0.f);
        o.y = xv.y + fmaxf(fmaf(hv.y, ss[cb + 1], sh[cb + 1]), 0.f);
        o.z = xv.z + fmaxf(fmaf(hv.z, ss[cb + 2], sh[cb + 2]), 0.f);
        o.w = xv.w + fmaxf(fmaf(hv.w, ss[cb + 3], sh[cb + 3]), 0.f);
        ((float4*)out)[idx] = o;
    }
}

// ---------------- launch ----------------
extern "C" void kernel_launch(void* const* d_in, const int* in_sizes, int n_in,
                              void* d_out, int out_size) {
    const float* x     = (const float*)d_in[0];
    const float* ea    = (const float*)d_in[1];
    const int*   ei    = (const int*)d_in[2];
    const float* Wg    = (const float*)d_in[3];
    const float* Wl    = (const float*)d_in[4];
    const float* gamma = (const float*)d_in[5];
    const float* beta  = (const float*)d_in[6];
    float* out = (float*)d_out;

    int n  = in_sizes[0] / CCH;
    int nE = in_sizes[2] / 2;
    int nb = (n + 127) / 128;

    static cudaStream_t s2 = nullptr;
    static cudaEvent_t ev0 = nullptr, ev1 = nullptr;
    if (s2 == nullptr) {
        cudaStreamCreate(&s2);
        cudaEventCreateWithFlags(&ev0, cudaEventDisableTiming);
        cudaEventCreateWithFlags(&ev1, cudaEventDisableTiming);
    }

    // fork: bucket build on s2, GEMM on legacy stream
    cudaEventRecord(ev0, 0);
    cudaStreamWaitEvent(s2, ev0, 0);

    k_zero<<<(n + 255) / 256, 256, 0, s2>>>(n);
    k_bucket<<<(nE + 255) / 256, 256, 0, s2>>>(ei, nE, n);
    cudaEventRecord(ev1, s2);

    k_gemm<<<2 * nb, 256>>>(x, Wg, Wl, n, nb);

    cudaStreamWaitEvent(0, ev1, 0);
    k_edge<<<(n + 3) / 4, 256>>>(ea, n);
    k_out<<<(n * (CCH / 4) + 255) / 256, 256>>>(x, gamma, beta, out, n);
}

// round 15
// speedup vs baseline: 1.5238x; 1.0274x over previous
#include <cuda_runtime.h>
#include <cuda_bf16.h>
#include <cstddef>
#include <cstdint>

#define NMAX 50000
#define EMAX 600000
#define CCH 128
#define SLOTS 64
#define WP 40   // smem stride in bf16 (80B) - conflict-free fragment LDS

// ---------------- scratch (static device globals; no allocation) -------------
__device__ float g_y[(size_t)NMAX * CCH];
__device__ float g_h[(size_t)NMAX * CCH];
__device__ int   g_cnt[NMAX];
__device__ int   g_slot[(size_t)NMAX * SLOTS];
__device__ int   g_src[(size_t)NMAX * SLOTS];
__device__ float g_sum[CCH];
__device__ float g_sumsq[CCH];

// ---------------- zero per-launch state ----------------
__global__ void k_zero(int n) {
    int i = blockIdx.x * blockDim.x + threadIdx.x;
    if (i < n) g_cnt[i] = 0;
    if (i < CCH) { g_sum[i] = 0.f; g_sumsq[i] = 0.f; }
}

// ---------------- bucket fill (slot = edge id, src prevalidated) -------------
__global__ void k_bucket(const int* __restrict__ ei, int nE, int n) {
    int e = blockIdx.x * blockDim.x + threadIdx.x;
    if (e < nE) {
        int t = ei[nE + e];                       // row 1 = target
        if ((unsigned)t < (unsigned)n) {
            int p = atomicAdd(&g_cnt[t], 1);
            if (p < SLOTS) {
                int s = ei[e];                    // row 0 = source
                if ((unsigned)s >= (unsigned)n) s = 0;
                g_slot[(size_t)t * SLOTS + p] = e;
                g_src [(size_t)t * SLOTS + p] = s;
            }
        }
    }
}

// ---------------- bf16 hi/lo split ----------------
__device__ __forceinline__ void split4(float4 v, uint2& h, uint2& l) {
    __nv_bfloat16 hx = __float2bfloat16(v.x);
    __nv_bfloat16 hy = __float2bfloat16(v.y);
    __nv_bfloat16 hz = __float2bfloat16(v.z);
    __nv_bfloat16 hw = __float2bfloat16(v.w);
    __nv_bfloat16 lx = __float2bfloat16(v.x - __bfloat162float(hx));
    __nv_bfloat16 ly = __float2bfloat16(v.y - __bfloat162float(hy));
    __nv_bfloat16 lz = __float2bfloat16(v.z - __bfloat162float(hz));
    __nv_bfloat16 lw = __float2bfloat16(v.w - __bfloat162float(hw));
    h.x = ((unsigned)__bfloat16_as_ushort(hy) << 16) | __bfloat16_as_ushort(hx);
    h.y = ((unsigned)__bfloat16_as_ushort(hw) << 16) | __bfloat16_as_ushort(hz);
    l.x = ((unsigned)__bfloat16_as_ushort(ly) << 16) | __bfloat16_as_ushort(lx);
    l.y = ((unsigned)__bfloat16_as_ushort(lw) << 16) | __bfloat16_as_ushort(lz);
}

// ---------------- dual GEMM via mma.sync bf16 (hi/lo split, fp32 accum) -----
__device__ __forceinline__ void mma_bf16(float* c, const unsigned* a, const unsigned* b) {
    asm volatile("mma.sync.aligned.m16n8k16.row.col.f32.bf16.bf16.f32 "
                 "{%0,%1,%2,%3}, {%4,%5,%6,%7}, {%8,%9}, {%0,%1,%2,%3};"
                 : "+f"(c[0]), "+f"(c[1]), "+f"(c[2]), "+f"(c[3])
                 : "r"(a[0]), "r"(a[1]), "r"(a[2]), "r"(a[3]),
                   "r"(b[0]), "r"(b[1]));
}

__global__ void __launch_bounds__(256, 2)
k_gemm(const float* __restrict__ x,
       const float* __restrict__ Wg,
       const float* __restrict__ Wl,
       int n, int nb) {
    __shared__ __nv_bfloat16 Ah[128 * WP], Al[128 * WP];
    __shared__ __nv_bfloat16 Bh[128 * WP], Bl[128 * WP];
    int tid = threadIdx.x;
    int pass = (blockIdx.x >= nb) ? 1 : 0;
    int row0 = (pass ? (blockIdx.x - nb) : blockIdx.x) * 128;
    const float* Wp = pass ? Wl : Wg;
    float* outp = pass ? g_h : g_y;
    int wid = tid >> 5, lane = tid & 31;
    int gq = lane >> 2, qq = lane & 3;
    int warpM = (wid & 3) * 32, warpN = (wid >> 2) * 64;

    float acc[2][8][4];
    #pragma unroll
    for (int m = 0; m < 2; m++)
        #pragma unroll
        for (int j = 0; j < 8; j++)
            #pragma unroll
            for (int q = 0; q < 4; q++) acc[m][j][q] = 0.f;

    for (int p = 0; p < 4; p++) {
        int k0 = p * 32;
        __syncthreads();
        for (int i = tid; i < 1024; i += 256) {
            int r = i >> 3, q = i & 7;
            int rr = row0 + r; if (rr >= n) rr = n - 1;
            float4 xv = *(const float4*)(x + (size_t)rr * CCH + k0 + q * 4);
            uint2 h, l;
            split4(xv, h, l);
            *(uint2*)(Ah + r * WP + q * 4) = h;
            *(uint2*)(Al + r * WP + q * 4) = l;
            float4 wv = *(const float4*)(Wp + (size_t)r * CCH + k0 + q * 4);
            split4(wv, h, l);
            *(uint2*)(Bh + r * WP + q * 4) = h;
            *(uint2*)(Bl + r * WP + q * 4) = l;
        }
        __syncthreads();

        #pragma unroll
        for (int ks = 0; ks < 2; ks++) {
            int kb = ks * 16;
            unsigned ah[2][4], al[2][4];
            #pragma unroll
            for (int m = 0; m < 2; m++) {
                int rb = warpM + m * 16 + gq;
                int o0 = rb * WP + kb + qq * 2;
                int o1 = (rb + 8) * WP + kb + qq * 2;
                ah[m][0] = *(const unsigned*)(Ah + o0);
                ah[m][1] = *(const unsigned*)(Ah + o1);
                ah[m][2] = *(const unsigned*)(Ah + o0 + 8);
                ah[m][3] = *(const unsigned*)(Ah + o1 + 8);
                al[m][0] = *(const unsigned*)(Al + o0);
                al[m][1] = *(const unsigned*)(Al + o1);
                al[m][2] = *(const unsigned*)(Al + o0 + 8);
                al[m][3] = *(const unsigned*)(Al + o1 + 8);
            }
            #pragma unroll
            for (int j = 0; j < 8; j++) {
                int cbp = (warpN + j * 8 + gq) * WP + kb + qq * 2;
                unsigned bh[2], bl[2];
                bh[0] = *(const unsigned*)(Bh + cbp);
                bh[1] = *(const unsigned*)(Bh + cbp + 8);
                bl[0] = *(const unsigned*)(Bl + cbp);
                bl[1] = *(const unsigned*)(Bl + cbp + 8);
                mma_bf16(acc[0][j], ah[0], bh);
                mma_bf16(acc[1][j], ah[1], bh);
                mma_bf16(acc[0][j], al[0], bh);
                mma_bf16(acc[1][j], al[1], bh);
                mma_bf16(acc[0][j], ah[0], bl);
                mma_bf16(acc[1][j], ah[1], bl);
            }
        }
    }

    #pragma unroll
    for (int m = 0; m < 2; m++) {
        int r = row0 + warpM + m * 16 + gq;
        #pragma unroll
        for (int j = 0; j < 8; j++) {
            int cc = warpN + j * 8 + qq * 2;
            if (r < n)
                *(float2*)(outp + (size_t)r * CCH + cc) =
                    make_float2(acc[m][j][0], acc[m][j][1]);
            if (r + 8 < n)
                *(float2*)(outp + (size_t)(r + 8) * CCH + cc) =
                    make_float2(acc[m][j][2], acc[m][j][3]);
        }
    }
}

// ---------------- fused edge attention + aggregation + BN partial stats -----
// Two warps per node (4-aligned split), batch-of-4 loop with NEXT-batch index
// prefetch; occupancy forced to 5 CTAs/SM via launch bounds.
__device__ __forceinline__ float sigf(float v) {
    return __fdividef(1.0f, 1.0f + __expf(-v));
}

__global__ void __launch_bounds__(256, 5)
k_edge(const float* __restrict__ edge_attr, int n) {
    __shared__ float s_sum[CCH];
    __shared__ float s_sq[CCH];
    __shared__ float4 sAgg[8][32];
    __shared__ float4 sDen[8][32];
    for (int i = threadIdx.x; i < CCH; i += 256) { s_sum[i] = 0.f; s_sq[i] = 0.f; }

    int wid  = threadIdx.x >> 5;
    int lane = threadIdx.x & 31;
    int node = blockIdx.x * 4 + (wid >> 1);
    int half = wid & 1;
    int cb   = lane * 4;

    float4 agg = make_float4(0.f, 0.f, 0.f, 0.f);
    float4 den = make_float4(0.f, 0.f, 0.f, 0.f);

    if (node < n) {
        int deg = g_cnt[node];
        if (deg > SLOTS) deg = SLOTS;
        int mid = ((deg >> 1) + 3) & ~3;          // 4-aligned split point
        if (mid > deg) mid = deg;
        int p0 = half ? mid : 0;
        int p1 = half ? deg : mid;
        const int* sp  = g_slot + (size_t)node * SLOTS;
        const int* srp = g_src  + (size_t)node * SLOTS;

        int p = p0;
        if (p + 4 <= p1) {
            int4 es = *(const int4*)(sp + p);
            int4 ss = *(const int4*)(srp + p);
            for (; p + 4 <= p1; ) {
                int pn = p + 4;
                int4 esn, ssn;
                if (pn + 4 <= p1) {               // prefetch next batch indices
                    esn = *(const int4*)(sp + pn);
                    ssn = *(const int4*)(srp + pn);
                }
                float4 va0 = __ldcs((const float4*)(edge_attr + (size_t)es.x * CCH + cb));
                float4 va1 = __ldcs((const float4*)(edge_attr + (size_t)es.y * CCH + cb));
                float4 va2 = __ldcs((const float4*)(edge_attr + (size_t)es.z * CCH + cb));
                float4 va3 = __ldcs((const float4*)(edge_attr + (size_t)es.w * CCH + cb));
                float4 vy0 = *(const float4*)(g_y + (size_t)ss.x * CCH + cb);
                float4 vy1 = *(const float4*)(g_y + (size_t)ss.y * CCH + cb);
                float4 vy2 = *(const float4*)(g_y + (size_t)ss.z * CCH + cb);
                float4 vy3 = *(const float4*)(g_y + (size_t)ss.w * CCH + cb);
                float g0, g1, g2, g3;
                g0 = sigf(va0.x); g1 = sigf(va1.x); g2 = sigf(va2.x); g3 = sigf(va3.x);
                den.x += (g0 + g1) + (g2 + g3);
                agg.x = fmaf(g0, vy0.x, fmaf(g1, vy1.x, fmaf(g2, vy2.x, fmaf(g3, vy3.x, agg.x))));
                g0 = sigf(va0.y); g1 = sigf(va1.y); g2 = sigf(va2.y); g3 = sigf(va3.y);
                den.y += (g0 + g1) + (g2 + g3);
                agg.y = fmaf(g0, vy0.y, fmaf(g1, vy1.y, fmaf(g2, vy2.y, fmaf(g3, vy3.y, agg.y))));
                g0 = sigf(va0.z); g1 = sigf(va1.z); g2 = sigf(va2.z); g3 = sigf(va3.z);
                den.z += (g0 + g1) + (g2 + g3);
                agg.z = fmaf(g0, vy0.z, fmaf(g1, vy1.z, fmaf(g2, vy2.z, fmaf(g3, vy3.z, agg.z))));
                g0 = sigf(va0.w); g1 = sigf(va1.w); g2 = sigf(va2.w); g3 = sigf(va3.w);
                den.w += (g0 + g1) + (g2 + g3);
                agg.w = fmaf(g0, vy0.w, fmaf(g1, vy1.w, fmaf(g2, vy2.w, fmaf(g3, vy3.w, agg.w))));
                p = pn;
                es = esn;
                ss = ssn;
            }
        }
        for (; p < p1; p++) {
            int e0 = sp[p], s0 = srp[p];
            float4 va = __ldcs((const float4*)(edge_attr + (size_t)e0 * CCH + cb));
            float4 vy = *(const float4*)(g_y + (size_t)s0 * CCH + cb);
            float gx = sigf(va.x), gy = sigf(va.y), gz = sigf(va.z), gw = sigf(va.w);
            den.x += gx;  den.y += gy;  den.z += gz;  den.w += gw;
            agg.x = fmaf(gx, vy.x, agg.x);
            agg.y = fmaf(gy, vy.y, agg.y);
            agg.z = fmaf(gz, vy.z, agg.z);
            agg.w = fmaf(gw, vy.w, agg.w);
        }
    }

    sAgg[wid][lane] = agg;
    sDen[wid][lane] = den;
    __syncthreads();

    if (node < n && half == 0) {
        float4 a2 = sAgg[wid + 1][lane];
        float4 d2 = sDen[wid + 1][lane];
        agg.x += a2.x;  agg.y += a2.y;  agg.z += a2.z;  agg.w += a2.w;
        den.x += d2.x;  den.y += d2.y;  den.z += d2.z;  den.w += d2.w;

        float4 hv = *(const float4*)(g_h + (size_t)node * CCH + cb);
        float4 h;
        h.x = hv.x + agg.x / (den.x + 1e-8f);
        h.y = hv.y + agg.y / (den.y + 1e-8f);
        h.z = hv.z + agg.z / (den.z + 1e-8f);
        h.w = hv.w + agg.w / (den.w + 1e-8f);
        *(float4*)(g_h + (size_t)node * CCH + cb) = h;

        atomicAdd(&s_sum[cb + 0], h.x);  atomicAdd(&s_sq[cb + 0], h.x * h.x);
        atomicAdd(&s_sum[cb + 1], h.y);  atomicAdd(&s_sq[cb + 1], h.y * h.y);
        atomicAdd(&s_sum[cb + 2], h.z);  atomicAdd(&s_sq[cb + 2], h.z * h.z);
        atomicAdd(&s_sum[cb + 3], h.w);  atomicAdd(&s_sq[cb + 3], h.w * h.w);
    }
    __syncthreads();
    if (threadIdx.x < CCH) {
        atomicAdd(&g_sum[threadIdx.x],   s_sum[threadIdx.x]);
        atomicAdd(&g_sumsq[threadIdx.x], s_sq[threadIdx.x]);
    }
}

// ---------------- epilogue with fused BN finalize ----------------
__global__ void k_out(const float* __restrict__ x,
                      const float* __restrict__ gamma,
                      const float* __restrict__ beta,
                      float* __restrict__ out, int n) {
    __shared__ float ss[CCH], sh[CCH];
    if (threadIdx.x < CCH) {
        int c = threadIdx.x;
        float invn = 1.0f / (float)n;
        float mean = g_sum[c] * invn;
        float var  = g_sumsq[c] * invn - mean * mean;
        float istd = rsqrtf(var + 1e-5f);
        float sc = istd * gamma[c];
        ss[c] = sc;
        sh[c] = beta[c] - mean * sc;
    }
    __syncthreads();
    int idx = blockIdx.x * blockDim.x + threadIdx.x;
    int total = n * (CCH / 4);
    if (idx < total) {
        int cb = (idx & (CCH / 4 - 1)) * 4;
        float4 xv = ((const float4*)x)[idx];
        float4 hv = ((const float4*)g_h)[idx];
        float4 o;
        o.x = xv.x + fmaxf(fmaf(hv.x, ss[cb + 0], sh[cb + 0]), 0.f);
        o.y = xv.y + fmaxf(fmaf(hv.y, ss[cb + 1], sh[cb + 1]), 0.f);
        o.z = xv.z + fmaxf(fmaf(hv.z, ss[cb + 2], sh[cb + 2]), 0.f);
        o.w = xv.w + fmaxf(fmaf(hv.w, ss[cb + 3], sh[cb + 3]), 0.f);
        ((float4*)out)[idx] = o;
    }
}

// ---------------- launch ----------------
extern "C" void kernel_launch(void* const* d_in, const int* in_sizes, int n_in,
                              void* d_out, int out_size) {
    const float* x     = (const float*)d_in[0];
    const float* ea    = (const float*)d_in[1];
    const int*   ei    = (const int*)d_in[2];
    const float* Wg    = (const float*)d_in[3];
    const float* Wl    = (const float*)d_in[4];
    const float* gamma = (const float*)d_in[5];
    const float* beta  = (const float*)d_in[6];
    float* out = (float*)d_out;

    int n  = in_sizes[0] / CCH;
    int nE = in_sizes[2] / 2;
    int nb = (n + 127) / 128;

    static cudaStream_t s2 = nullptr;
    static cudaEvent_t ev0 = nullptr, ev1 = nullptr;
    if (s2 == nullptr) {
        cudaStreamCreate(&s2);
        cudaEventCreateWithFlags(&ev0, cudaEventDisableTiming);
        cudaEventCreateWithFlags(&ev1, cudaEventDisableTiming);
    }

    // fork: bucket build on s2, GEMM on legacy stream
    cudaEventRecord(ev0, 0);
    cudaStreamWaitEvent(s2, ev0, 0);

    k_zero<<<(n + 255) / 256, 256, 0, s2>>>(n);
    k_bucket<<<(nE + 255) / 256, 256, 0, s2>>>(ei, nE, n);
    cudaEventRecord(ev1, s2);

    k_gemm<<<2 * nb, 256>>>(x, Wg, Wl, n, nb);

    cudaStreamWaitEvent(0, ev1, 0);
    k_edge<<<(n + 3) / 4, 256>>>(ea, n);
    k_out<<<(n * (CCH / 4) + 255) / 256, 256>>>(x, gamma, beta, out, n);
}